// round 14
// baseline (speedup 1.0000x reference)
#include <cuda_runtime.h>
#include <cstdint>

// Problem: out[N=100000,128] = zeros; out[i1]+=deltas[:,:128]; out[i2]+=deltas[:,128:256];
//          b = deltas[:,256:320].  d_out layout: [ out : N*128 fp32 ][ b : E*64 fp32 ]
//
// R13 = R3 (best: 145.7us scatter) + SMEM index prefetch. The i1/i2 loads used to
// sit AFTER the fence.proxy.async on lane 0 (asm memory clobbers pin them there),
// putting a ~600cyc L2/DRAM miss on the TMA-issue critical path every iteration.
// Now a one-time prologue loads each warp's <=31 index pairs into SMEM (one pair
// per lane, full MLP); the loop reads them with a 29cyc LDS instead.

#define WARPS_PER_BLOCK 8
#define THREADS_PER_BLOCK (WARPS_PER_BLOCK * 32)
#define GRID_BLOCKS 2048

__device__ __forceinline__ uint64_t make_evict_last_policy() {
    uint64_t pol;
    asm("createpolicy.fractional.L2::evict_last.b64 %0, 1.0;" : "=l"(pol));
    return pol;
}

__device__ __forceinline__ uint64_t make_evict_first_policy() {
    uint64_t pol;
    asm("createpolicy.fractional.L2::evict_first.b64 %0, 1.0;" : "=l"(pol));
    return pol;
}

__global__ void zero_out_kernel(float4* __restrict__ out4, long n4) {
    long i = blockIdx.x * (long)blockDim.x + threadIdx.x;
    if (i < n4) {
        uint64_t pol = make_evict_last_policy();
        asm volatile("st.global.L2::cache_hint.v4.f32 [%0], {%1,%2,%3,%4}, %5;"
                     :: "l"(out4 + i), "f"(0.f), "f"(0.f), "f"(0.f), "f"(0.f), "l"(pol)
                     : "memory");
    }
}

__device__ __forceinline__ float4 ldg_stream(const float4* p, uint64_t pol) {
    float4 v;
    asm("ld.global.nc.L2::cache_hint.v4.f32 {%0,%1,%2,%3}, [%4], %5;"
        : "=f"(v.x), "=f"(v.y), "=f"(v.z), "=f"(v.w) : "l"(p), "l"(pol));
    return v;
}

__device__ __forceinline__ void stg_stream(float4* p, float4 v) {
    asm volatile("st.global.cs.v4.f32 [%0], {%1,%2,%3,%4};"
                 :: "l"(p), "f"(v.x), "f"(v.y), "f"(v.z), "f"(v.w)
                 : "memory");
}

__device__ __forceinline__ void bulk_reduce_add_f32(float* gdst, uint32_t ssrc,
                                                    uint32_t bytes, uint64_t pol) {
    asm volatile(
        "cp.reduce.async.bulk.global.shared::cta.bulk_group.L2::cache_hint.add.f32 "
        "[%0], [%1], %2, %3;"
        :: "l"(gdst), "r"(ssrc), "r"(bytes), "l"(pol)
        : "memory");
}

__global__ void __launch_bounds__(THREADS_PER_BLOCK, 8)
scatter_kernel(const float4* __restrict__ deltas4,  // E * 80 float4
               const int*    __restrict__ i1,       // E
               const int*    __restrict__ i2,       // E
               float*        __restrict__ out,      // N * 128 fp32
               float4*       __restrict__ bout4,    // E * 16 float4
               long E, long nwarps)
{
    // Per-warp double buffer: 2 x 64 float4 = 2 KB/warp, 16 KB/block.
    __shared__ __align__(16) float4 buf[WARPS_PER_BLOCK][2][64];
    // Prefetched index pairs: one per iteration (<=32 iters/warp at this grid).
    __shared__ int2 sidx[WARPS_PER_BLOCK][32];

    const int wid  = threadIdx.x >> 5;
    const int lane = threadIdx.x & 31;
    const long gw  = (long)blockIdx.x * WARPS_PER_BLOCK + wid;

    const uint64_t pol_ef = make_evict_first_policy();
    const uint64_t pol_el = make_evict_last_policy();

    // Prologue: lane l prefetches the (i1,i2) pair for this warp's l-th edge.
    {
        long ee = gw + (long)lane * nwarps;
        if (ee < E)
            sidx[wid][lane] = make_int2(__ldg(&i1[ee]), __ldg(&i2[ee]));
    }
    __syncwarp();

    int parity = 0;
    int k = 0;
    for (long e = gw; e < E; e += nwarps, parity ^= 1, ++k) {
        // Reclaim this parity's buffer (handed to TMA 2 iterations ago).
        if (lane == 0)
            asm volatile("cp.async.bulk.wait_group.read 1;" ::: "memory");
        __syncwarp();

        const float4* row = deltas4 + e * 80;

        // ux: chunks [0,32) ; uy: chunks [32,64) -> SMEM (coalesced)
        float4 v0 = ldg_stream(row + lane,      pol_ef);
        float4 v1 = ldg_stream(row + 32 + lane, pol_ef);
        buf[wid][parity][lane]      = v0;
        buf[wid][parity][32 + lane] = v1;

        // b: chunks [64,80) -> straight to output, bypass SMEM
        if (lane < 16) {
            float4 vb = ldg_stream(row + 64 + lane, pol_ef);
            stg_stream(bout4 + e * 16 + lane, vb);
        }
        __syncwarp();

        if (lane == 0) {
            // 29-cycle LDS instead of a ~600-cycle dependent LDG.
            int2 rr = (k < 32) ? sidx[wid][k]
                               : make_int2(__ldg(&i1[e]), __ldg(&i2[e]));
            asm volatile("fence.proxy.async.shared::cta;" ::: "memory");
            uint32_t s = (uint32_t)__cvta_generic_to_shared(&buf[wid][parity][0]);
            bulk_reduce_add_f32(out + (long)rr.x * 128, s,       512, pol_el);
            bulk_reduce_add_f32(out + (long)rr.y * 128, s + 512, 512, pol_el);
            asm volatile("cp.async.bulk.commit_group;" ::: "memory");
        }
    }

    // Drain all pending bulk groups before exit.
    if (lane == 0)
        asm volatile("cp.async.bulk.wait_group 0;" ::: "memory");
}

extern "C" void kernel_launch(void* const* d_in, const int* in_sizes, int n_in,
                              void* d_out, int out_size)
{
    // metadata order: unary(N*128 f32), binary(E*64 f32), deltas(E*320 f32),
    //                 index1(E i32), index2(E i32)
    const long N = in_sizes[0] / 128;
    const long E = in_sizes[2] / 320;

    const float4* deltas4 = (const float4*)d_in[2];
    const int*    i1      = (const int*)d_in[3];
    const int*    i2      = (const int*)d_in[4];

    float*  out   = (float*)d_out;                       // N*128
    float4* bout4 = (float4*)((float*)d_out + N * 128);  // E*16 float4

    // 1) zero the scatter target and pin it in L2 (evict_last)
    {
        long n4 = (N * 128) / 4;
        int  threads = 256;
        long blocks = (n4 + threads - 1) / threads;
        zero_out_kernel<<<(unsigned)blocks, threads>>>((float4*)out, n4);
    }

    // 2) scatter-add (TMA bulk-reduce, SMEM-prefetched indices) + b copy
    {
        long nwarps = (long)GRID_BLOCKS * WARPS_PER_BLOCK;
        scatter_kernel<<<GRID_BLOCKS, THREADS_PER_BLOCK>>>(deltas4, i1, i2, out, bout4, E, nwarps);
    }
}

// round 15
// speedup vs baseline: 1.3256x; 1.3256x over previous
#include <cuda_runtime.h>
#include <cstdint>

// Problem: out[N=100000,128] = zeros; out[i1]+=deltas[:,:128]; out[i2]+=deltas[:,128:256];
//          b = deltas[:,256:320].  d_out layout: [ out : N*128 fp32 ][ b : E*64 fp32 ]
//
// R14: hybrid at BLOCK granularity. Even blocks = R3's TMA bulk-reduce body
// (best single-mechanism: 145.7us). Odd blocks = R2's REDG body (red.global.v4,
// LSU pipe, 159us standalone). Each mechanism carries half the edges on its own
// hardware unit, concurrently across resident blocks; R9 showed mixing them
// INSIDE one warp's in-order stream fails, so the mix is per-block (uniform
// branch, zero divergence). Both should now sit under the ~137us DRAM floor.

#define WARPS_PER_BLOCK 8
#define THREADS_PER_BLOCK (WARPS_PER_BLOCK * 32)
#define GRID_BLOCKS 2048

__device__ __forceinline__ uint64_t make_evict_last_policy() {
    uint64_t pol;
    asm("createpolicy.fractional.L2::evict_last.b64 %0, 1.0;" : "=l"(pol));
    return pol;
}

__device__ __forceinline__ uint64_t make_evict_first_policy() {
    uint64_t pol;
    asm("createpolicy.fractional.L2::evict_first.b64 %0, 1.0;" : "=l"(pol));
    return pol;
}

__global__ void zero_out_kernel(float4* __restrict__ out4, long n4) {
    long i = blockIdx.x * (long)blockDim.x + threadIdx.x;
    if (i < n4) {
        uint64_t pol = make_evict_last_policy();
        asm volatile("st.global.L2::cache_hint.v4.f32 [%0], {%1,%2,%3,%4}, %5;"
                     :: "l"(out4 + i), "f"(0.f), "f"(0.f), "f"(0.f), "f"(0.f), "l"(pol)
                     : "memory");
    }
}

__device__ __forceinline__ float4 ldg_stream(const float4* p, uint64_t pol) {
    float4 v;
    asm("ld.global.nc.L2::cache_hint.v4.f32 {%0,%1,%2,%3}, [%4], %5;"
        : "=f"(v.x), "=f"(v.y), "=f"(v.z), "=f"(v.w) : "l"(p), "l"(pol));
    return v;
}

__device__ __forceinline__ void stg_stream(float4* p, float4 v) {
    asm volatile("st.global.cs.v4.f32 [%0], {%1,%2,%3,%4};"
                 :: "l"(p), "f"(v.x), "f"(v.y), "f"(v.z), "f"(v.w)
                 : "memory");
}

__device__ __forceinline__ void red_add_v4_el(float* p, float4 v, uint64_t pol) {
    asm volatile("red.global.add.L2::cache_hint.v4.f32 [%0], {%1,%2,%3,%4}, %5;"
                 :: "l"(p), "f"(v.x), "f"(v.y), "f"(v.z), "f"(v.w), "l"(pol)
                 : "memory");
}

__device__ __forceinline__ void bulk_reduce_add_f32(float* gdst, uint32_t ssrc,
                                                    uint32_t bytes, uint64_t pol) {
    asm volatile(
        "cp.reduce.async.bulk.global.shared::cta.bulk_group.L2::cache_hint.add.f32 "
        "[%0], [%1], %2, %3;"
        :: "l"(gdst), "r"(ssrc), "r"(bytes), "l"(pol)
        : "memory");
}

__global__ void __launch_bounds__(THREADS_PER_BLOCK, 8)
scatter_kernel(const float4* __restrict__ deltas4,  // E * 80 float4
               const int*    __restrict__ i1,       // E
               const int*    __restrict__ i2,       // E
               float*        __restrict__ out,      // N * 128 fp32
               float4*       __restrict__ bout4,    // E * 16 float4
               long E, long nwarps)
{
    // Per-warp double buffer (used only by TMA blocks): 16 KB/block.
    __shared__ __align__(16) float4 buf[WARPS_PER_BLOCK][2][64];

    const int wid  = threadIdx.x >> 5;
    const int lane = threadIdx.x & 31;
    const long gw  = (long)blockIdx.x * WARPS_PER_BLOCK + wid;

    const uint64_t pol_ef = make_evict_first_policy();
    const uint64_t pol_el = make_evict_last_policy();

    if ((blockIdx.x & 1) == 0) {
        // ── TMA bulk-reduce mechanism (exact R3 body) ──
        int parity = 0;
        for (long e = gw; e < E; e += nwarps, parity ^= 1) {
            if (lane == 0)
                asm volatile("cp.async.bulk.wait_group.read 1;" ::: "memory");
            __syncwarp();

            const float4* row = deltas4 + e * 80;

            float4 v0 = ldg_stream(row + lane,      pol_ef);
            float4 v1 = ldg_stream(row + 32 + lane, pol_ef);
            buf[wid][parity][lane]      = v0;
            buf[wid][parity][32 + lane] = v1;

            if (lane < 16) {
                float4 vb = ldg_stream(row + 64 + lane, pol_ef);
                stg_stream(bout4 + e * 16 + lane, vb);
            }
            __syncwarp();

            if (lane == 0) {
                asm volatile("fence.proxy.async.shared::cta;" ::: "memory");
                int r1 = __ldg(&i1[e]);
                int r2 = __ldg(&i2[e]);
                uint32_t s = (uint32_t)__cvta_generic_to_shared(&buf[wid][parity][0]);
                bulk_reduce_add_f32(out + (long)r1 * 128, s,       512, pol_el);
                bulk_reduce_add_f32(out + (long)r2 * 128, s + 512, 512, pol_el);
                asm volatile("cp.async.bulk.commit_group;" ::: "memory");
            }
        }
        if (lane == 0)
            asm volatile("cp.async.bulk.wait_group 0;" ::: "memory");
    } else {
        // ── REDG mechanism (LSU pipe; no smem, no fences, no waits) ──
        for (long e = gw; e < E; e += nwarps) {
            const float4* row = deltas4 + e * 80;

            float4 v0 = ldg_stream(row + lane,      pol_ef);
            float4 v1 = ldg_stream(row + 32 + lane, pol_ef);
            int r1 = __ldg(&i1[e]);
            int r2 = __ldg(&i2[e]);

            red_add_v4_el(out + (long)r1 * 128 + lane * 4, v0, pol_el);
            red_add_v4_el(out + (long)r2 * 128 + lane * 4, v1, pol_el);

            if (lane < 16) {
                float4 vb = ldg_stream(row + 64 + lane, pol_ef);
                stg_stream(bout4 + e * 16 + lane, vb);
            }
        }
    }
}

extern "C" void kernel_launch(void* const* d_in, const int* in_sizes, int n_in,
                              void* d_out, int out_size)
{
    // metadata order: unary(N*128 f32), binary(E*64 f32), deltas(E*320 f32),
    //                 index1(E i32), index2(E i32)
    const long N = in_sizes[0] / 128;
    const long E = in_sizes[2] / 320;

    const float4* deltas4 = (const float4*)d_in[2];
    const int*    i1      = (const int*)d_in[3];
    const int*    i2      = (const int*)d_in[4];

    float*  out   = (float*)d_out;                       // N*128
    float4* bout4 = (float4*)((float*)d_out + N * 128);  // E*16 float4

    // 1) zero the scatter target and pin it in L2 (evict_last)
    {
        long n4 = (N * 128) / 4;
        int  threads = 256;
        long blocks = (n4 + threads - 1) / threads;
        zero_out_kernel<<<(unsigned)blocks, threads>>>((float4*)out, n4);
    }

    // 2) scatter-add: even blocks TMA-reduce, odd blocks REDG + b copy
    {
        long nwarps = (long)GRID_BLOCKS * WARPS_PER_BLOCK;
        scatter_kernel<<<GRID_BLOCKS, THREADS_PER_BLOCK>>>(deltas4, i1, i2, out, bout4, E, nwarps);
    }
}